// round 10
// baseline (speedup 1.0000x reference)
#include <cuda_runtime.h>
#include <cuda_bf16.h>
#include <cstdint>

// Problem constants
#define BB 32
#define CC 64
#define NN 16384
#define GCHUNKS 32
#define GCN 512            // NN / GCHUNKS

// ---------------- scratch (device globals; no allocation allowed) ----------
__device__ float g_partial[BB * GCHUNKS * CC * CC];       // partial Grams
__device__ __align__(16) unsigned short g_Ahi[BB * 4096]; // bf16 A images [c][d]
__device__ __align__(16) unsigned short g_Alo[BB * 4096];
__device__ float g_scale;                                 // gamma / sigma

// ---------------- helpers ---------------------------------------------------
__device__ __forceinline__ uint32_t smem_u32(const void* p) {
    uint32_t a;
    asm("{ .reg .u64 t; cvta.to.shared.u64 t, %1; cvt.u32.u64 %0, t; }"
        : "=r"(a) : "l"(p));
    return a;
}

__device__ __forceinline__ void ldsm4(uint32_t* r, uint32_t addr) {
    asm volatile("ldmatrix.sync.aligned.m8n8.x4.shared.b16 {%0,%1,%2,%3}, [%4];"
                 : "=r"(r[0]), "=r"(r[1]), "=r"(r[2]), "=r"(r[3]) : "r"(addr));
}
__device__ __forceinline__ void ldsm4t(uint32_t* r, uint32_t addr) {
    asm volatile("ldmatrix.sync.aligned.m8n8.x4.trans.shared.b16 {%0,%1,%2,%3}, [%4];"
                 : "=r"(r[0]), "=r"(r[1]), "=r"(r[2]), "=r"(r[3]) : "r"(addr));
}
__device__ __forceinline__ void mma16816(float* d, const uint32_t* a,
                                         uint32_t b0, uint32_t b1) {
    asm volatile(
        "mma.sync.aligned.m16n8k16.row.col.f32.bf16.bf16.f32 "
        "{%0,%1,%2,%3}, {%4,%5,%6,%7}, {%8,%9}, {%0,%1,%2,%3};"
        : "+f"(d[0]), "+f"(d[1]), "+f"(d[2]), "+f"(d[3])
        : "r"(a[0]), "r"(a[1]), "r"(a[2]), "r"(a[3]), "r"(b0), "r"(b1));
}

// split two f32 into packed bf16 hi-pair and lo-pair (truncation split:
// hi = upper 16 bits; lo = exact remainder truncated -> total err ~2^-16)
__device__ __forceinline__ void split2(float v0, float v1,
                                       uint32_t& hp, uint32_t& lp) {
    uint32_t b0 = __float_as_uint(v0), b1 = __float_as_uint(v1);
    hp = (b0 >> 16) | (b1 & 0xFFFF0000u);
    float l0 = v0 - __uint_as_float(b0 & 0xFFFF0000u);
    float l1 = v1 - __uint_as_float(b1 & 0xFFFF0000u);
    lp = (__float_as_uint(l0) >> 16) | (__float_as_uint(l1) & 0xFFFF0000u);
}

// ---------------- Kernel A: spectral norm scale ----------------------------
__global__ void sigma_kernel(const float* __restrict__ W,
                             const float* __restrict__ gamma,
                             const float* __restrict__ u) {
    __shared__ float sv[CC];
    __shared__ float red[CC];
    int c = threadIdx.x; // 64 threads

    float vt = 0.f;
    #pragma unroll 8
    for (int r = 0; r < CC; r++) vt += W[r * CC + c] * u[r];
    red[c] = vt * vt;
    __syncthreads();
    if (c == 0) {
        float s = 0.f;
        for (int i = 0; i < CC; i++) s += red[i];
        red[0] = 1.f / fmaxf(sqrtf(s), 1e-12f);
    }
    __syncthreads();
    float inv = red[0];
    sv[c] = vt * inv;
    __syncthreads();

    float wv = 0.f;
    #pragma unroll 8
    for (int k = 0; k < CC; k++) wv += W[c * CC + k] * sv[k];
    red[c] = wv * wv;
    __syncthreads();
    if (c == 0) {
        float s2 = 0.f;
        for (int i = 0; i < CC; i++) s2 += red[i];
        float sigma = s2 / fmaxf(sqrtf(s2), 1e-12f);
        g_scale = gamma[0] / sigma;
    }
}

// ---------------- Kernel B: Gram partials via HMMA (mma.sync) ---------------
// grid (GCHUNKS, BB), 128 threads (4 warps: 2x2 warp grid, 32x32 per warp).
// D[m][n] = sum_k X[m][k] X[n][k], both fragments from the same smem tile.
__global__ void __launch_bounds__(128) gram_mma(const float* __restrict__ x) {
    __shared__ __align__(16) unsigned short hiT[64][72]; // [channel][k] bf16 hi
    __shared__ __align__(16) unsigned short loT[64][72]; // lo
    const int tid = threadIdx.x, warp = tid >> 5, lane = tid & 31;
    const int wm = warp & 1, wn = warp >> 1;
    const int chunk = blockIdx.x, b = blockIdx.y;
    const float* xb = x + (size_t)b * CC * NN + (size_t)chunk * GCN;

    float acc[8][4]; // [rs*4 + g*2 + h][4]
    #pragma unroll
    for (int i = 0; i < 8; i++)
        #pragma unroll
        for (int j = 0; j < 4; j++) acc[i][j] = 0.f;

    const int mat = lane >> 3, mr = lane & 7; // ldmatrix x4 lane roles

    for (int s = 0; s < 8; s++) { // 8 stages of 64 k
        __syncthreads();
        #pragma unroll
        for (int k = 0; k < 8; k++) {
            int e = tid + k * 128;     // 0..1023
            int c = e >> 4;            // channel 0..63
            int k4 = (e & 15) * 4;     // k offset 0..60
            float4 v = *(const float4*)&xb[(size_t)c * NN + s * 64 + k4];
            uint32_t h0, l0, h1, l1;
            split2(v.x, v.y, h0, l0);
            split2(v.z, v.w, h1, l1);
            *(uint2*)&hiT[c][k4] = make_uint2(h0, h1);
            *(uint2*)&loT[c][k4] = make_uint2(l0, l1);
        }
        __syncthreads();
        #pragma unroll
        for (int ks = 0; ks < 4; ks++) { // k16 steps within stage
            int acol = ks * 16 + ((mat >> 1) << 3);
            uint32_t ah[2][4], al[2][4];
            #pragma unroll
            for (int rs = 0; rs < 2; rs++) {
                int arow = 32 * wm + 16 * rs + ((mat & 1) << 3) + mr;
                ldsm4(ah[rs], smem_u32(&hiT[arow][acol]));
                ldsm4(al[rs], smem_u32(&loT[arow][acol]));
            }
            #pragma unroll
            for (int g = 0; g < 2; g++) { // two 16-col groups in this half
                uint32_t bh[4], bl[4];
                int brow = 32 * wn + 16 * g + ((mat & 1) << 3) + mr;
                ldsm4(bh, smem_u32(&hiT[brow][acol]));
                ldsm4(bl, smem_u32(&loT[brow][acol]));
                #pragma unroll
                for (int rs = 0; rs < 2; rs++) {
                    float* a0 = acc[rs * 4 + g * 2];
                    float* a1 = acc[rs * 4 + g * 2 + 1];
                    mma16816(a0, ah[rs], bh[0], bh[2]);
                    mma16816(a0, ah[rs], bl[0], bl[2]);
                    mma16816(a0, al[rs], bh[0], bh[2]);
                    mma16816(a1, ah[rs], bh[1], bh[3]);
                    mma16816(a1, ah[rs], bl[1], bl[3]);
                    mma16816(a1, al[rs], bh[1], bh[3]);
                }
            }
        }
    }

    // epilogue: D-frag -> g_partial[b][chunk][row][col]
    float* gp = g_partial + ((size_t)b * GCHUNKS + chunk) * 4096;
    int t2 = (lane & 3) * 2;
    #pragma unroll
    for (int rs = 0; rs < 2; rs++) {
        int r0 = 32 * wm + 16 * rs + (lane >> 2);
        #pragma unroll
        for (int g = 0; g < 2; g++)
            #pragma unroll
            for (int h = 0; h < 2; h++) {
                int col = 32 * wn + 16 * g + 8 * h + t2;
                float* a = acc[rs * 4 + g * 2 + h];
                *(float2*)&gp[r0 * 64 + col]       = make_float2(a[0], a[1]);
                *(float2*)&gp[(r0 + 8) * 64 + col] = make_float2(a[2], a[3]);
            }
    }
}

// ---------------- Kernel C: A = (gamma/sigma) * G * W -> bf16 hi/lo images --
// grid (4 slices, BB), 256 threads. Slice = 16 rows of A. Output row-major
// [c][d] bf16 hi/lo for out_mma's ldmatrix fragment loads.
__global__ void __launch_bounds__(256) afuse_kernel(const float* __restrict__ W) {
    __shared__ float Gs[16][68];
    __shared__ float Ws[CC][68];
    const int tid = threadIdx.x;
    const int slice = blockIdx.x; // 0..3
    const int b = blockIdx.y;     // 0..31
    const int row_l = tid >> 4;       // 0..15
    const int c4 = (tid & 15) * 4;    // col base

    float4 acc = make_float4(0.f, 0.f, 0.f, 0.f);
    for (int k = 0; k < GCHUNKS; k++) {
        const float* gp = g_partial + ((size_t)b * GCHUNKS + k) * 4096
                          + (slice * 16 + row_l) * 64 + c4;
        float4 v = *(const float4*)gp;
        acc.x += v.x; acc.y += v.y; acc.z += v.z; acc.w += v.w;
    }
    *(float4*)&Gs[row_l][c4] = acc;

    #pragma unroll
    for (int l = 0; l < 16; l++) {
        int idx = tid + l * 256; // 0..4095
        Ws[idx >> 6][idx & 63] = W[idx];
    }
    __syncthreads();

    float a0 = 0.f, a1 = 0.f, a2 = 0.f, a3 = 0.f;
    #pragma unroll 8
    for (int k = 0; k < CC; k++) {
        float g = Gs[row_l][k];
        float4 w = *(const float4*)&Ws[k][c4];
        a0 += g * w.x; a1 += g * w.y; a2 += g * w.z; a3 += g * w.w;
    }

    float s = g_scale;
    int grow = slice * 16 + row_l;
    uint32_t hp0, lp0, hp1, lp1;
    split2(s * a0, s * a1, hp0, lp0);
    split2(s * a2, s * a3, hp1, lp1);
    size_t off = (size_t)b * 4096 + grow * 64 + c4;
    *(uint2*)&g_Ahi[off] = make_uint2(hp0, hp1);
    *(uint2*)&g_Alo[off] = make_uint2(lp0, lp1);
}

// ---------------- Kernel D: out = A @ x + x via HMMA ------------------------
// grid (64 nblk, BB), 256 threads (8 warps: 2 M x 4 N, 32x64 per warp).
// Block tile: 64 c x 256 n. B = x[d][n] staged naturally; ldmatrix.trans.
#define OUT_SMEM 86016
__global__ void __launch_bounds__(256) out_mma(const float* __restrict__ x,
                                               float* __restrict__ out) {
    extern __shared__ __align__(16) unsigned char sm[];
    typedef unsigned short (*arr72)[72];
    typedef unsigned short (*arr264)[264];
    arr72 Ah   = (arr72)(sm);                    //  9216 B
    arr72 Al   = (arr72)(sm + 9216);             //  9216 B
    arr264 Bh  = (arr264)(sm + 18432);           // 33792 B
    arr264 Bl  = (arr264)(sm + 18432 + 33792);   // 33792 B

    const int tid = threadIdx.x, warp = tid >> 5, lane = tid & 31;
    const int wm = warp & 1, wn = warp >> 1;     // wm 0..1, wn 0..3
    const int nblk = blockIdx.x, b = blockIdx.y;
    const float* xb = x + (size_t)b * CC * NN + (size_t)nblk * 256;
    float* ob = out + (size_t)b * CC * NN + (size_t)nblk * 256;

    // stage A images (already bf16, row-major [c][d])
    const uint4* AhG = (const uint4*)(g_Ahi + (size_t)b * 4096);
    const uint4* AlG = (const uint4*)(g_Alo + (size_t)b * 4096);
    #pragma unroll
    for (int k = 0; k < 2; k++) {
        int e = tid + k * 256;       // 0..511
        int c = e >> 3, d8 = (e & 7) * 8;
        *(uint4*)&Ah[c][d8] = AhG[e];
        *(uint4*)&Al[c][d8] = AlG[e];
    }
    // stage B: x[d][n] f32 -> bf16 hi/lo, natural layout (coalesced)
    #pragma unroll
    for (int k = 0; k < 16; k++) {
        int e = tid + k * 256;       // 0..4095
        int d = e >> 6, n4 = (e & 63) * 4;
        float4 v = *(const float4*)&xb[(size_t)d * NN + n4];
        uint32_t h0, l0, h1, l1;
        split2(v.x, v.y, h0, l0);
        split2(v.z, v.w, h1, l1);
        *(uint2*)&Bh[d][n4] = make_uint2(h0, h1);
        *(uint2*)&Bl[d][n4] = make_uint2(l0, l1);
    }
    __syncthreads();

    float acc[16][4]; // [rs*8 + g][4]: rs row-slice (16 rows), g n8-pair group
    #pragma unroll
    for (int i = 0; i < 16; i++)
        #pragma unroll
        for (int j = 0; j < 4; j++) acc[i][j] = 0.f;

    const int mat = lane >> 3, mr = lane & 7;
    #pragma unroll
    for (int ks = 0; ks < 4; ks++) { // k = d, 4 x 16
        int acol = ks * 16 + ((mat >> 1) << 3);
        uint32_t ah[2][4], al[2][4];
        #pragma unroll
        for (int rs = 0; rs < 2; rs++) {
            int arow = 32 * wm + 16 * rs + ((mat & 1) << 3) + mr;
            ldsm4(ah[rs], smem_u32(&Ah[arow][acol]));
            ldsm4(al[rs], smem_u32(&Al[arow][acol]));
        }
        int drow = ks * 16 + ((mat & 1) << 3) + mr;
        #pragma unroll
        for (int gq = 0; gq < 4; gq++) { // four 16-col groups in 64-col half
            uint32_t bh[4], bl[4];
            int ncol = 64 * wn + 16 * gq + ((mat >> 1) << 3);
            ldsm4t(bh, smem_u32(&Bh[drow][ncol]));
            ldsm4t(bl, smem_u32(&Bl[drow][ncol]));
            #pragma unroll
            for (int rs = 0; rs < 2; rs++) {
                float* a0 = acc[rs * 8 + 2 * gq];
                float* a1 = acc[rs * 8 + 2 * gq + 1];
                mma16816(a0, ah[rs], bh[0], bh[1]);
                mma16816(a0, ah[rs], bl[0], bl[1]);
                mma16816(a0, al[rs], bh[0], bh[1]);
                mma16816(a1, ah[rs], bh[2], bh[3]);
                mma16816(a1, ah[rs], bl[2], bl[3]);
                mma16816(a1, al[rs], bh[2], bh[3]);
            }
        }
    }

    // epilogue: residual add (exact f32 from global, L1/L2-hot) + store
    int t2 = (lane & 3) * 2;
    #pragma unroll
    for (int rs = 0; rs < 2; rs++) {
        int c0 = 32 * wm + 16 * rs + (lane >> 2);
        #pragma unroll
        for (int g = 0; g < 8; g++) {
            int col = 64 * wn + 8 * g + t2;
            float* a = acc[rs * 8 + g];
            float2 x0 = *(const float2*)&xb[(size_t)c0 * NN + col];
            float2 x1 = *(const float2*)&xb[(size_t)(c0 + 8) * NN + col];
            *(float2*)&ob[(size_t)c0 * NN + col] =
                make_float2(a[0] + x0.x, a[1] + x0.y);
            *(float2*)&ob[(size_t)(c0 + 8) * NN + col] =
                make_float2(a[2] + x1.x, a[3] + x1.y);
        }
    }
}

// ---------------- launch ----------------------------------------------------
extern "C" void kernel_launch(void* const* d_in, const int* in_sizes, int n_in,
                              void* d_out, int out_size) {
    const float* x     = (const float*)d_in[0]; // [32,64,128,128]
    const float* W     = (const float*)d_in[1]; // [64,64]
    const float* gamma = (const float*)d_in[2]; // [1]
    const float* u     = (const float*)d_in[3]; // [64]
    float* out = (float*)d_out;

    cudaFuncSetAttribute(out_mma, cudaFuncAttributeMaxDynamicSharedMemorySize,
                         OUT_SMEM);

    sigma_kernel<<<1, 64>>>(W, gamma, u);

    dim3 gg(GCHUNKS, BB);
    gram_mma<<<gg, 128>>>(x);

    dim3 ga(4, BB);
    afuse_kernel<<<ga, 256>>>(W);

    dim3 go(NN / 256, BB);
    out_mma<<<go, 256, OUT_SMEM>>>(x, out);
}

// round 14
// speedup vs baseline: 1.0982x; 1.0982x over previous
#include <cuda_runtime.h>
#include <cuda_bf16.h>
#include <cstdint>

// Problem constants
#define BB 32
#define CC 64
#define NN 16384
#define GCHUNKS 32
#define GCN 512            // NN / GCHUNKS

// ---------------- scratch (device globals; no allocation allowed) ----------
__device__ float g_partial[BB * GCHUNKS * CC * CC];       // partial Grams
__device__ __align__(16) unsigned short g_Ahi[BB * 4096]; // bf16 A images [c][d]
__device__ __align__(16) unsigned short g_Alo[BB * 4096];
__device__ float g_scale;                                 // gamma / sigma

// ---------------- helpers ---------------------------------------------------
__device__ __forceinline__ uint32_t smem_u32(const void* p) {
    uint32_t a;
    asm("{ .reg .u64 t; cvta.to.shared.u64 t, %1; cvt.u32.u64 %0, t; }"
        : "=r"(a) : "l"(p));
    return a;
}

__device__ __forceinline__ void ldsm4(uint32_t* r, uint32_t addr) {
    asm volatile("ldmatrix.sync.aligned.m8n8.x4.shared.b16 {%0,%1,%2,%3}, [%4];"
                 : "=r"(r[0]), "=r"(r[1]), "=r"(r[2]), "=r"(r[3]) : "r"(addr));
}
__device__ __forceinline__ void ldsm4t(uint32_t* r, uint32_t addr) {
    asm volatile("ldmatrix.sync.aligned.m8n8.x4.trans.shared.b16 {%0,%1,%2,%3}, [%4];"
                 : "=r"(r[0]), "=r"(r[1]), "=r"(r[2]), "=r"(r[3]) : "r"(addr));
}
__device__ __forceinline__ void mma16816(float* d, const uint32_t* a,
                                         uint32_t b0, uint32_t b1) {
    asm volatile(
        "mma.sync.aligned.m16n8k16.row.col.f32.bf16.bf16.f32 "
        "{%0,%1,%2,%3}, {%4,%5,%6,%7}, {%8,%9}, {%0,%1,%2,%3};"
        : "+f"(d[0]), "+f"(d[1]), "+f"(d[2]), "+f"(d[3])
        : "r"(a[0]), "r"(a[1]), "r"(a[2]), "r"(a[3]), "r"(b0), "r"(b1));
}

// split two f32 into packed bf16 hi-pair and lo-pair (truncation split:
// hi = upper 16 bits; lo = exact remainder truncated -> total err ~2^-16)
__device__ __forceinline__ void split2(float v0, float v1,
                                       uint32_t& hp, uint32_t& lp) {
    uint32_t b0 = __float_as_uint(v0), b1 = __float_as_uint(v1);
    hp = (b0 >> 16) | (b1 & 0xFFFF0000u);
    float l0 = v0 - __uint_as_float(b0 & 0xFFFF0000u);
    float l1 = v1 - __uint_as_float(b1 & 0xFFFF0000u);
    lp = (__float_as_uint(l0) >> 16) | (__float_as_uint(l1) & 0xFFFF0000u);
}

// ---------------- Kernel A: spectral norm scale ----------------------------
__global__ void sigma_kernel(const float* __restrict__ W,
                             const float* __restrict__ gamma,
                             const float* __restrict__ u) {
    __shared__ float sv[CC];
    __shared__ float red[CC];
    int c = threadIdx.x; // 64 threads

    float vt = 0.f;
    #pragma unroll 8
    for (int r = 0; r < CC; r++) vt += W[r * CC + c] * u[r];
    red[c] = vt * vt;
    __syncthreads();
    if (c == 0) {
        float s = 0.f;
        for (int i = 0; i < CC; i++) s += red[i];
        red[0] = 1.f / fmaxf(sqrtf(s), 1e-12f);
    }
    __syncthreads();
    float inv = red[0];
    sv[c] = vt * inv;
    __syncthreads();

    float wv = 0.f;
    #pragma unroll 8
    for (int k = 0; k < CC; k++) wv += W[c * CC + k] * sv[k];
    red[c] = wv * wv;
    __syncthreads();
    if (c == 0) {
        float s2 = 0.f;
        for (int i = 0; i < CC; i++) s2 += red[i];
        float sigma = s2 / fmaxf(sqrtf(s2), 1e-12f);
        g_scale = gamma[0] / sigma;
    }
}

// ---------------- Kernel B: Gram partials via HMMA (mma.sync) ---------------
// grid (GCHUNKS, BB), 64 threads (2 warps). Warp w: rows 32w..32w+31 x all 64
// cols. ldsm/mma = 0.25. Small CTA -> many resident CTAs hide latency.
__global__ void __launch_bounds__(64) gram_mma(const float* __restrict__ x) {
    __shared__ __align__(16) unsigned short hiT[64][72]; // [channel][k] bf16 hi
    __shared__ __align__(16) unsigned short loT[64][72]; // lo
    const int tid = threadIdx.x, warp = tid >> 5, lane = tid & 31;
    const int chunk = blockIdx.x, b = blockIdx.y;
    const float* xb = x + (size_t)b * CC * NN + (size_t)chunk * GCN;

    float acc[16][4]; // [rs*8 + g*2 + h][4]; rs: two 16-row slices, 8 n8 groups
    #pragma unroll
    for (int i = 0; i < 16; i++)
        #pragma unroll
        for (int j = 0; j < 4; j++) acc[i][j] = 0.f;

    const int mat = lane >> 3, mr = lane & 7; // ldmatrix x4 lane roles

    for (int s = 0; s < 8; s++) { // 8 stages of 64 k
        __syncthreads();
        #pragma unroll
        for (int k = 0; k < 16; k++) {
            int e = tid + k * 64;      // 0..1023
            int c = e >> 4;            // channel 0..63
            int k4 = (e & 15) * 4;     // k offset 0..60
            float4 v = *(const float4*)&xb[(size_t)c * NN + s * 64 + k4];
            uint32_t h0, l0, h1, l1;
            split2(v.x, v.y, h0, l0);
            split2(v.z, v.w, h1, l1);
            *(uint2*)&hiT[c][k4] = make_uint2(h0, h1);
            *(uint2*)&loT[c][k4] = make_uint2(l0, l1);
        }
        __syncthreads();
        #pragma unroll
        for (int ks = 0; ks < 4; ks++) { // k16 steps within stage
            int acol = ks * 16 + ((mat >> 1) << 3);
            uint32_t ah[2][4], al[2][4];
            #pragma unroll
            for (int rs = 0; rs < 2; rs++) {
                int arow = 32 * warp + 16 * rs + ((mat & 1) << 3) + mr;
                ldsm4(ah[rs], smem_u32(&hiT[arow][acol]));
                ldsm4(al[rs], smem_u32(&loT[arow][acol]));
            }
            #pragma unroll
            for (int g = 0; g < 4; g++) { // four 16-col B groups (full 64)
                uint32_t bh[4], bl[4];
                int brow = 16 * g + ((mat & 1) << 3) + mr;
                ldsm4(bh, smem_u32(&hiT[brow][acol]));
                ldsm4(bl, smem_u32(&loT[brow][acol]));
                #pragma unroll
                for (int rs = 0; rs < 2; rs++) {
                    float* a0 = acc[rs * 8 + g * 2];
                    float* a1 = acc[rs * 8 + g * 2 + 1];
                    mma16816(a0, ah[rs], bh[0], bh[2]);
                    mma16816(a0, ah[rs], bl[0], bl[2]);
                    mma16816(a0, al[rs], bh[0], bh[2]);
                    mma16816(a1, ah[rs], bh[1], bh[3]);
                    mma16816(a1, ah[rs], bl[1], bl[3]);
                    mma16816(a1, al[rs], bh[1], bh[3]);
                }
            }
        }
    }

    // epilogue: D-frag -> g_partial[b][chunk][row][col]
    float* gp = g_partial + ((size_t)b * GCHUNKS + chunk) * 4096;
    int t2 = (lane & 3) * 2;
    #pragma unroll
    for (int rs = 0; rs < 2; rs++) {
        int r0 = 32 * warp + 16 * rs + (lane >> 2);
        #pragma unroll
        for (int g = 0; g < 4; g++)
            #pragma unroll
            for (int h = 0; h < 2; h++) {
                int col = 16 * g + 8 * h + t2;
                float* a = acc[rs * 8 + g * 2 + h];
                *(float2*)&gp[r0 * 64 + col]       = make_float2(a[0], a[1]);
                *(float2*)&gp[(r0 + 8) * 64 + col] = make_float2(a[2], a[3]);
            }
    }
}

// ---------------- Kernel C: A = (gamma/sigma) * G * W -> bf16 hi/lo images --
// grid (4 slices, BB), 256 threads. Slice = 16 rows of A. Output row-major
// [c][d] bf16 hi/lo for out_mma's ldmatrix fragment loads.
__global__ void __launch_bounds__(256) afuse_kernel(const float* __restrict__ W) {
    __shared__ float Gs[16][68];
    __shared__ float Ws[CC][68];
    const int tid = threadIdx.x;
    const int slice = blockIdx.x; // 0..3
    const int b = blockIdx.y;     // 0..31
    const int row_l = tid >> 4;       // 0..15
    const int c4 = (tid & 15) * 4;    // col base

    float4 acc = make_float4(0.f, 0.f, 0.f, 0.f);
    for (int k = 0; k < GCHUNKS; k++) {
        const float* gp = g_partial + ((size_t)b * GCHUNKS + k) * 4096
                          + (slice * 16 + row_l) * 64 + c4;
        float4 v = *(const float4*)gp;
        acc.x += v.x; acc.y += v.y; acc.z += v.z; acc.w += v.w;
    }
    *(float4*)&Gs[row_l][c4] = acc;

    #pragma unroll
    for (int l = 0; l < 16; l++) {
        int idx = tid + l * 256; // 0..4095
        Ws[idx >> 6][idx & 63] = W[idx];
    }
    __syncthreads();

    float a0 = 0.f, a1 = 0.f, a2 = 0.f, a3 = 0.f;
    #pragma unroll 8
    for (int k = 0; k < CC; k++) {
        float g = Gs[row_l][k];
        float4 w = *(const float4*)&Ws[k][c4];
        a0 += g * w.x; a1 += g * w.y; a2 += g * w.z; a3 += g * w.w;
    }

    float s = g_scale;
    int grow = slice * 16 + row_l;
    uint32_t hp0, lp0, hp1, lp1;
    split2(s * a0, s * a1, hp0, lp0);
    split2(s * a2, s * a3, hp1, lp1);
    size_t off = (size_t)b * 4096 + grow * 64 + c4;
    *(uint2*)&g_Ahi[off] = make_uint2(hp0, hp1);
    *(uint2*)&g_Alo[off] = make_uint2(lp0, lp1);
}

// ---------------- Kernel D: out = A @ x + x via HMMA ------------------------
// grid (64 nblk, BB), 256 threads (8 warps: 2 M x 4 N, 32x64 per warp).
// Block tile: 64 c x 256 n. __launch_bounds__(256, 2) caps regs at 128 so
// TWO CTAs fit per SM (RF was the R10 occupancy killer at 134 regs).
#define OUT_SMEM 86016
__global__ void __launch_bounds__(256, 2) out_mma(const float* __restrict__ x,
                                                  float* __restrict__ out) {
    extern __shared__ __align__(16) unsigned char sm[];
    typedef unsigned short (*arr72)[72];
    typedef unsigned short (*arr264)[264];
    arr72 Ah   = (arr72)(sm);                    //  9216 B
    arr72 Al   = (arr72)(sm + 9216);             //  9216 B
    arr264 Bh  = (arr264)(sm + 18432);           // 33792 B
    arr264 Bl  = (arr264)(sm + 18432 + 33792);   // 33792 B

    const int tid = threadIdx.x, warp = tid >> 5, lane = tid & 31;
    const int wm = warp & 1, wn = warp >> 1;     // wm 0..1, wn 0..3
    const int nblk = blockIdx.x, b = blockIdx.y;
    const float* xb = x + (size_t)b * CC * NN + (size_t)nblk * 256;
    float* ob = out + (size_t)b * CC * NN + (size_t)nblk * 256;

    // stage A images (already bf16, row-major [c][d])
    const uint4* AhG = (const uint4*)(g_Ahi + (size_t)b * 4096);
    const uint4* AlG = (const uint4*)(g_Alo + (size_t)b * 4096);
    #pragma unroll
    for (int k = 0; k < 2; k++) {
        int e = tid + k * 256;       // 0..511
        int c = e >> 3, d8 = (e & 7) * 8;
        *(uint4*)&Ah[c][d8] = AhG[e];
        *(uint4*)&Al[c][d8] = AlG[e];
    }
    // stage B: x[d][n] f32 -> bf16 hi/lo, natural layout (coalesced).
    // split2 results stored immediately to keep the live set small.
    #pragma unroll
    for (int k = 0; k < 16; k++) {
        int e = tid + k * 256;       // 0..4095
        int d = e >> 6, n4 = (e & 63) * 4;
        float4 v = *(const float4*)&xb[(size_t)d * NN + n4];
        uint32_t h0, l0;
        split2(v.x, v.y, h0, l0);
        *(uint32_t*)&Bh[d][n4] = h0;
        *(uint32_t*)&Bl[d][n4] = l0;
        split2(v.z, v.w, h0, l0);
        *(uint32_t*)&Bh[d][n4 + 2] = h0;
        *(uint32_t*)&Bl[d][n4 + 2] = l0;
    }
    __syncthreads();

    float acc[16][4]; // [rs*8 + g][4]: rs row-slice (16 rows), g n8-pair group
    #pragma unroll
    for (int i = 0; i < 16; i++)
        #pragma unroll
        for (int j = 0; j < 4; j++) acc[i][j] = 0.f;

    const int mat = lane >> 3, mr = lane & 7;
    #pragma unroll
    for (int ks = 0; ks < 4; ks++) { // k = d, 4 x 16
        int acol = ks * 16 + ((mat >> 1) << 3);
        uint32_t ah[2][4], al[2][4];
        #pragma unroll
        for (int rs = 0; rs < 2; rs++) {
            int arow = 32 * wm + 16 * rs + ((mat & 1) << 3) + mr;
            ldsm4(ah[rs], smem_u32(&Ah[arow][acol]));
            ldsm4(al[rs], smem_u32(&Al[arow][acol]));
        }
        int drow = ks * 16 + ((mat & 1) << 3) + mr;
        #pragma unroll
        for (int gq = 0; gq < 4; gq++) { // four 16-col groups in 64-col half
            uint32_t bh[4], bl[4];
            int ncol = 64 * wn + 16 * gq + ((mat >> 1) << 3);
            ldsm4t(bh, smem_u32(&Bh[drow][ncol]));
            ldsm4t(bl, smem_u32(&Bl[drow][ncol]));
            #pragma unroll
            for (int rs = 0; rs < 2; rs++) {
                float* a0 = acc[rs * 8 + 2 * gq];
                float* a1 = acc[rs * 8 + 2 * gq + 1];
                mma16816(a0, ah[rs], bh[0], bh[1]);
                mma16816(a0, ah[rs], bl[0], bl[1]);
                mma16816(a0, al[rs], bh[0], bh[1]);
                mma16816(a1, ah[rs], bh[2], bh[3]);
                mma16816(a1, ah[rs], bl[2], bl[3]);
                mma16816(a1, al[rs], bh[2], bh[3]);
            }
        }
    }

    // epilogue: residual add (exact f32 from global, L1/L2-hot) + store
    int t2 = (lane & 3) * 2;
    #pragma unroll
    for (int rs = 0; rs < 2; rs++) {
        int c0 = 32 * wm + 16 * rs + (lane >> 2);
        #pragma unroll
        for (int g = 0; g < 8; g++) {
            int col = 64 * wn + 8 * g + t2;
            float* a = acc[rs * 8 + g];
            float2 x0 = *(const float2*)&xb[(size_t)c0 * NN + col];
            float2 x1 = *(const float2*)&xb[(size_t)(c0 + 8) * NN + col];
            *(float2*)&ob[(size_t)c0 * NN + col] =
                make_float2(a[0] + x0.x, a[1] + x0.y);
            *(float2*)&ob[(size_t)(c0 + 8) * NN + col] =
                make_float2(a[2] + x1.x, a[3] + x1.y);
        }
    }
}

// ---------------- launch ----------------------------------------------------
extern "C" void kernel_launch(void* const* d_in, const int* in_sizes, int n_in,
                              void* d_out, int out_size) {
    const float* x     = (const float*)d_in[0]; // [32,64,128,128]
    const float* W     = (const float*)d_in[1]; // [64,64]
    const float* gamma = (const float*)d_in[2]; // [1]
    const float* u     = (const float*)d_in[3]; // [64]
    float* out = (float*)d_out;

    (void)cudaFuncSetAttribute(out_mma,
                               cudaFuncAttributeMaxDynamicSharedMemorySize,
                               OUT_SMEM);

    sigma_kernel<<<1, 64>>>(W, gamma, u);

    dim3 gg(GCHUNKS, BB);
    gram_mma<<<gg, 64>>>(x);

    dim3 ga(4, BB);
    afuse_kernel<<<ga, 256>>>(W);

    dim3 go(NN / 256, BB);
    out_mma<<<go, 256, OUT_SMEM>>>(x, out);
}